// round 15
// baseline (speedup 1.0000x reference)
#include <cuda_runtime.h>
#include <cstdint>

// Problem constants (fixed-shape problem)
#define DDIM   512          // feature dim
#define BNUM   64           // batch / segment count
#define LSEQ   2048         // max_length
#define ACC_ELEMS (BNUM * DDIM)   // 32768 floats = 128 KB
#define K1_GRID 148         // one CTA per SM, single wave
#define K1_THREADS 512      // each thread owns exactly ONE float column
#define UB 8                // nodes per pipeline batch (double-buffered)
#define MAX_CHUNK 688       // > ceil(100000/148) = 676, padded (mult of 8)

#define ACC_BYTES   (ACC_ELEMS * 4)
// smem layout after the 128 KB accumulator:
#define OFF_SIDX    ACC_BYTES                         // int2 [MAX_CHUNK]
#define OFF_SB      (OFF_SIDX + MAX_CHUNK * 8)        // int2 [MAX_CHUNK] (sorted)
#define OFF_HIST    (OFF_SB + MAX_CHUNK * 8)          // int  [BNUM]
#define OFF_BASE    (OFF_HIST + BNUM * 4)             // int  [BNUM]
#define OFF_SNODE   (OFF_BASE + BNUM * 4)             // u16  [MAX_CHUNK] (sorted node ids)
#define OFF_PERM    (OFF_SNODE + MAX_CHUNK * 2)       // u16  [MAX_CHUNK]
#define SMEM_BYTES  (OFF_PERM + MAX_CHUNK * 2)

// Scratch (allocation-free: __device__ globals)
__device__ float g_partials[K1_GRID * ACC_ELEMS];   // ~19.4 MB
__device__ float g_x[ACC_ELEMS];                    // final [64, 512]

__global__ void __launch_bounds__(K1_THREADS, 1)
k1_accum(const float* __restrict__ gcn, const void* __restrict__ tp, int nnodes) {
    extern __shared__ float sacc[];                        // 128 KB accumulator
    int2*           sidx  = (int2*)((char*)sacc + OFF_SIDX);
    int2*           sb    = (int2*)((char*)sacc + OFF_SB);
    int*            shist = (int*)((char*)sacc + OFF_HIST);
    int*            sbase = (int*)((char*)sacc + OFF_BASE);
    unsigned short* snode = (unsigned short*)((char*)sacc + OFF_SNODE);
    unsigned short* sperm = (unsigned short*)((char*)sacc + OFF_PERM);
    const int tid = threadIdx.x;

    // zero private accumulator + histogram
    {
        float4* z = (float4*)sacc;
#pragma unroll
        for (int i = tid; i < ACC_ELEMS / 4; i += K1_THREADS)
            z[i] = make_float4(0.f, 0.f, 0.f, 0.f);
        if (tid < BNUM) shist[tid] = 0;
    }

    // Runtime index-dtype detection: values are in [0, 64). If the buffer is
    // int32 but read as u64, a sample is >= 2^32 with prob 63/64 per probe.
    __shared__ int s_is64;
    if (tid == 0) {
        const unsigned long long* p = (const unsigned long long*)tp;
        int f = 1;
        for (int j = 0; j < 64; ++j)
            if (p[j] >= 64ull) { f = 0; break; }
        s_is64 = f;
    }
    __syncthreads();

    const int chunk = (nnodes + K1_GRID - 1) / K1_GRID;
    const int i0 = blockIdx.x * chunk;
    const int i1 = min(i0 + chunk, nnodes);
    const int cnt = max(i1 - i0, 0);

    // Stage this CTA's index pairs to smem as int2 (dtype resolved once)
    if (s_is64) {
        const longlong2* p = (const longlong2*)tp;
        for (int j = tid; j < cnt; j += K1_THREADS) {
            longlong2 t = __ldg(p + (i0 + j));
            sidx[j] = make_int2((int)t.x, (int)t.y);
        }
    } else {
        const int2* p = (const int2*)tp;
        for (int j = tid; j < cnt; j += K1_THREADS)
            sidx[j] = __ldg(p + (i0 + j));
    }
    __syncthreads();

    // ---- counting sort by b1 (stable -> bitwise deterministic) ----
    // histogram (order-independent integer adds: deterministic)
    for (int j = tid; j < cnt; j += K1_THREADS)
        atomicAdd(&shist[sidx[j].x], 1);
    __syncthreads();
    if (tid == 0) {                     // exclusive prefix over 64 buckets
        int run = 0;
#pragma unroll
        for (int b = 0; b < BNUM; ++b) { sbase[b] = run; run += shist[b]; }
    }
    __syncthreads();
    // stable scatter: thread t (< 64) owns bucket t, scans ascending j
    if (tid < BNUM) {
        int pos = sbase[tid];
        for (int j = 0; j < cnt; ++j)
            if (sidx[j].x == tid) sperm[pos++] = (unsigned short)j;
    }
    __syncthreads();
    // gather into sorted staging (parallel, deterministic)
    for (int j = tid; j < cnt; j += K1_THREADS) {
        const int p = sperm[j];
        snode[j] = (unsigned short)p;
        sb[j] = sidx[p];
    }
    __syncthreads();

    // ---- hot loop: b1 runs accumulate in a register (no smem chain);
    //      only b2 does a per-node smem RMW. Double-buffered LDG batches. ----
    const float* gh = gcn + (size_t)i0 * DDIM + tid;

    float racc = 0.f;
    int run_b = -1;

    float va[UB], vb[UB];
    int2  ba[UB], bb[UB];
    int   na[UB], nb_[UB];

#define LOADI(NN, BB, base)                                                 \
    {                                                                       \
        _Pragma("unroll")                                                   \
        for (int u = 0; u < UB; ++u) NN[u] = snode[(base) + u];             \
        _Pragma("unroll")                                                   \
        for (int u = 0; u < UB; ++u) BB[u] = sb[(base) + u];                \
    }
#define LOADV(VV, NN)                                                       \
    {                                                                       \
        _Pragma("unroll")                                                   \
        for (int u = 0; u < UB; ++u)                                        \
            VV[u] = __ldg(gh + (size_t)NN[u] * DDIM);                       \
    }
#define PROC(VV, BB)                                                        \
    {                                                                       \
        _Pragma("unroll")                                                   \
        for (int u = 0; u < UB; ++u) {                                      \
            if (BB[u].x != run_b) {            /* warp-uniform, rare */     \
                if (run_b >= 0) sacc[run_b * DDIM + tid] += racc;           \
                run_b = BB[u].x; racc = 0.f;                                \
            }                                                               \
            racc += VV[u];                                                  \
            sacc[BB[u].y * DDIM + tid] += VV[u];                            \
        }                                                                   \
    }

    const int nfull = cnt / UB;
    int k = 0;
    if (nfull > 0) { LOADI(na, ba, 0); LOADV(va, na); }
    for (; k + 2 <= nfull; k += 2) {
        LOADI(nb_, bb, (k + 1) * UB); LOADV(vb, nb_);
        PROC(va, ba);
        if (k + 2 < nfull) { LOADI(na, ba, (k + 2) * UB); LOADV(va, na); }
        PROC(vb, bb);
    }
    if (k < nfull) PROC(va, ba);
    for (int j = nfull * UB; j < cnt; ++j) {     // tail
        const int p = snode[j];
        const int2 b = sb[j];
        const float v = __ldg(gh + (size_t)p * DDIM);
        if (b.x != run_b) {
            if (run_b >= 0) sacc[run_b * DDIM + tid] += racc;
            run_b = b.x; racc = 0.f;
        }
        racc += v;
        sacc[b.y * DDIM + tid] += v;
    }
    if (run_b >= 0) sacc[run_b * DDIM + tid] += racc;   // final run flush

#undef LOADI
#undef LOADV
#undef PROC

    __syncthreads();
    // flush private partial (zeros if this CTA had an empty range)
    float4* dst = (float4*)(g_partials + (size_t)blockIdx.x * ACC_ELEMS);
    const float4* src = (const float4*)sacc;
#pragma unroll
    for (int i = tid; i < ACC_ELEMS / 4; i += K1_THREADS)
        dst[i] = src[i];
}

// ---------------------------------------------------------------------------
// K2: reduce 148 partials -> g_x. Fully coalesced, deterministic order.
// ---------------------------------------------------------------------------
__global__ void __launch_bounds__(256) k2_reduce() {
    const int idx = blockIdx.x * 256 + threadIdx.x;   // 0 .. 32767
    float s = 0.f;
#pragma unroll 4
    for (int c = 0; c < K1_GRID; ++c)
        s += g_partials[(size_t)c * ACC_ELEMS + idx];
    g_x[idx] = s;
}

// ---------------------------------------------------------------------------
// K3: broadcast x[b,:] across L. Each CTA handles (b, 64 rows of L); each
// thread caches its float4 of the row in a register and streams it out with
// __stcs stores (write-once data, no L2 residency pressure).
// ---------------------------------------------------------------------------
__global__ void __launch_bounds__(256) k3_bcast(float* __restrict__ out) {
    const int b = blockIdx.y;
    const int l0 = blockIdx.x * 64;

    const int j = threadIdx.x & 127;    // float4 column 0..127
    const int r = threadIdx.x >> 7;     // row parity (0/1)
    const float4 v = __ldg((const float4*)(g_x + b * DDIM) + j);

    float4* o = (float4*)out + ((size_t)b * LSEQ + l0 + r) * (DDIM / 4) + j;
#pragma unroll
    for (int l = 0; l < 64; l += 2) {
        __stcs(o, v);
        o += 2 * (DDIM / 4);
    }
}

// ---------------------------------------------------------------------------
// Launch. Inputs (metadata order): gcn_hidden f32 [N*512], token_position
// int64/int32 [2N], batch_size, max_length, token_position2 (unused).
// ---------------------------------------------------------------------------
extern "C" void kernel_launch(void* const* d_in, const int* in_sizes, int n_in,
                              void* d_out, int out_size) {
    const float* gcn = (const float*)d_in[0];
    const void*  tp  = d_in[1];
    const int nnodes = in_sizes[0] / DDIM;   // N = 100000

    cudaFuncSetAttribute(k1_accum, cudaFuncAttributeMaxDynamicSharedMemorySize,
                         SMEM_BYTES);

    k1_accum<<<K1_GRID, K1_THREADS, SMEM_BYTES>>>(gcn, tp, nnodes);
    k2_reduce<<<ACC_ELEMS / 256, 256>>>();
    dim3 g3(LSEQ / 64, BNUM);
    k3_bcast<<<g3, 256>>>((float*)d_out);
}

// round 16
// speedup vs baseline: 1.0117x; 1.0117x over previous
#include <cuda_runtime.h>
#include <cstdint>

// Problem constants (fixed-shape problem)
#define DDIM   512          // feature dim
#define BNUM   64           // batch / segment count
#define LSEQ   2048         // max_length
#define ACC_ELEMS (BNUM * DDIM)   // 32768 floats = 128 KB
#define K1_GRID 148         // one CTA per SM, single wave
#define K1_THREADS 512      // each thread owns exactly ONE float column
#define UB 16               // nodes per pipeline batch (double-buffered)
#define MAX_CHUNK 704       // > ceil(100000/148) = 676, multiple of 32

#define ACC_BYTES   (ACC_ELEMS * 4)
// smem: 128 KB accumulator + packed u16 index pairs
#define OFF_SPK     ACC_BYTES                         // u16 [MAX_CHUNK]
#define SMEM_BYTES  (OFF_SPK + MAX_CHUNK * 2)

// Scratch (allocation-free: __device__ globals)
__device__ float g_partials[K1_GRID * ACC_ELEMS];   // ~19.4 MB
__device__ float g_x[ACC_ELEMS];                    // final [64, 512]

__global__ void __launch_bounds__(K1_THREADS, 1)
k1_accum(const float* __restrict__ gcn, const void* __restrict__ tp, int nnodes) {
    extern __shared__ float sacc[];                      // 128 KB accumulator
    unsigned short* spk = (unsigned short*)((char*)sacc + OFF_SPK);
    const int tid = threadIdx.x;

    // zero private accumulator (+ pad the packed-index tail so batch reads
    // of the last partial batch hit benign zeros)
    {
        float4* z = (float4*)sacc;
#pragma unroll
        for (int i = tid; i < ACC_ELEMS / 4; i += K1_THREADS)
            z[i] = make_float4(0.f, 0.f, 0.f, 0.f);
        if (tid < MAX_CHUNK / 2) ((unsigned int*)spk)[tid] = 0;
    }

    // Runtime index-dtype detection: values are in [0, 64). If the buffer is
    // int32 but read as u64, a sample is >= 2^32 with prob 63/64 per probe.
    // 64 probes => misdetection prob (1/64)^64 ~ 0.
    __shared__ int s_is64;
    if (tid == 0) {
        const unsigned long long* p = (const unsigned long long*)tp;
        int f = 1;
        for (int j = 0; j < 64; ++j)
            if (p[j] >= 64ull) { f = 0; break; }
        s_is64 = f;
    }
    __syncthreads();

    const int chunk = (nnodes + K1_GRID - 1) / K1_GRID;
    const int i0 = blockIdx.x * chunk;
    const int i1 = min(i0 + chunk, nnodes);
    const int cnt = max(i1 - i0, 0);

    // Stage this CTA's index pairs to smem, packed as u16 = b1 | (b2 << 8)
    if (s_is64) {
        const longlong2* p = (const longlong2*)tp;
        for (int j = tid; j < cnt; j += K1_THREADS) {
            longlong2 t = __ldg(p + (i0 + j));
            spk[j] = (unsigned short)(((unsigned)t.x) | (((unsigned)t.y) << 8));
        }
    } else {
        const int2* p = (const int2*)tp;
        for (int j = tid; j < cnt; j += K1_THREADS) {
            int2 t = __ldg(p + (i0 + j));
            spk[j] = (unsigned short)(((unsigned)t.x) | (((unsigned)t.y) << 8));
        }
    }
    __syncthreads();

    // ---- hot loop: double-buffered 16-node batches. Deep LDG pipeline
    //      (up to 32 lines in flight per warp) to cover DRAM latency; two
    //      unconditional smem RMWs per node (b1==b2 is correct as two
    //      sequential adds by the same thread). ----
    const float* gh = gcn + (size_t)i0 * DDIM + tid;

    float va[UB], vb[UB];
    unsigned int pa[UB / 2], pb[UB / 2];   // 2 packed nodes per u32

#define LOADB(VV, PP, base)                                                 \
    {                                                                       \
        _Pragma("unroll")                                                   \
        for (int u = 0; u < UB; ++u)                                        \
            VV[u] = __ldg(gh + (size_t)((base) + u) * DDIM);                \
        const unsigned int* w = (const unsigned int*)(spk + (base));        \
        _Pragma("unroll")                                                   \
        for (int u = 0; u < UB / 2; ++u) PP[u] = w[u];                      \
    }
#define PROCB(VV, PP)                                                       \
    {                                                                       \
        _Pragma("unroll")                                                   \
        for (int u = 0; u < UB; ++u) {                                      \
            const unsigned int wrd = PP[u >> 1] >> ((u & 1) * 16);          \
            const int b1 = wrd & 0xff;                                      \
            const int b2 = (wrd >> 8) & 0xff;                               \
            sacc[b1 * DDIM + tid] += VV[u];                                 \
            sacc[b2 * DDIM + tid] += VV[u];                                 \
        }                                                                   \
    }

    const int nfull = cnt / UB;
    int k = 0;
    if (nfull > 0) LOADB(va, pa, 0);
    for (; k + 2 <= nfull; k += 2) {
        LOADB(vb, pb, (k + 1) * UB);
        PROCB(va, pa);
        if (k + 2 < nfull) LOADB(va, pa, (k + 2) * UB);
        PROCB(vb, pb);
    }
    if (k < nfull) PROCB(va, pa);   // odd batch, already loaded

    // tail nodes
    for (int j = nfull * UB; j < cnt; ++j) {
        const float v = __ldg(gh + (size_t)j * DDIM);
        const unsigned int wrd = spk[j];
        const int b1 = wrd & 0xff;
        const int b2 = (wrd >> 8) & 0xff;
        sacc[b1 * DDIM + tid] += v;
        sacc[b2 * DDIM + tid] += v;
    }

#undef LOADB
#undef PROCB

    __syncthreads();
    // flush private partial (zeros if this CTA had an empty range)
    float4* dst = (float4*)(g_partials + (size_t)blockIdx.x * ACC_ELEMS);
    const float4* src = (const float4*)sacc;
#pragma unroll
    for (int i = tid; i < ACC_ELEMS / 4; i += K1_THREADS)
        dst[i] = src[i];
}

// ---------------------------------------------------------------------------
// K2: reduce 148 partials -> g_x. Fully coalesced, deterministic order.
// ---------------------------------------------------------------------------
__global__ void __launch_bounds__(256) k2_reduce() {
    const int idx = blockIdx.x * 256 + threadIdx.x;   // 0 .. 32767
    float s = 0.f;
#pragma unroll 4
    for (int c = 0; c < K1_GRID; ++c)
        s += g_partials[(size_t)c * ACC_ELEMS + idx];
    g_x[idx] = s;
}

// ---------------------------------------------------------------------------
// K3: broadcast x[b,:] across L. Each CTA handles (b, 64 rows of L); each
// thread caches its float4 of the row in a register and streams it out with
// __stcs stores (write-once data, no L2 residency pressure).
// ---------------------------------------------------------------------------
__global__ void __launch_bounds__(256) k3_bcast(float* __restrict__ out) {
    const int b = blockIdx.y;
    const int l0 = blockIdx.x * 64;

    const int j = threadIdx.x & 127;    // float4 column 0..127
    const int r = threadIdx.x >> 7;     // row parity (0/1)
    const float4 v = __ldg((const float4*)(g_x + b * DDIM) + j);

    float4* o = (float4*)out + ((size_t)b * LSEQ + l0 + r) * (DDIM / 4) + j;
#pragma unroll
    for (int l = 0; l < 64; l += 2) {
        __stcs(o, v);
        o += 2 * (DDIM / 4);
    }
}

// ---------------------------------------------------------------------------
// Launch. Inputs (metadata order): gcn_hidden f32 [N*512], token_position
// int64/int32 [2N], batch_size, max_length, token_position2 (unused).
// ---------------------------------------------------------------------------
extern "C" void kernel_launch(void* const* d_in, const int* in_sizes, int n_in,
                              void* d_out, int out_size) {
    const float* gcn = (const float*)d_in[0];
    const void*  tp  = d_in[1];
    const int nnodes = in_sizes[0] / DDIM;   // N = 100000

    cudaFuncSetAttribute(k1_accum, cudaFuncAttributeMaxDynamicSharedMemorySize,
                         SMEM_BYTES);

    k1_accum<<<K1_GRID, K1_THREADS, SMEM_BYTES>>>(gcn, tp, nnodes);
    k2_reduce<<<ACC_ELEMS / 256, 256>>>();
    dim3 g3(LSEQ / 64, BNUM);
    k3_bcast<<<g3, 256>>>((float*)d_out);
}

// round 17
// speedup vs baseline: 1.1397x; 1.1265x over previous
#include <cuda_runtime.h>
#include <cstdint>

// Problem constants (fixed-shape problem)
#define DDIM   512          // feature dim
#define BNUM   64           // batch / segment count
#define LSEQ   2048         // max_length
#define ACC_ELEMS (BNUM * DDIM)   // 32768 floats = 128 KB
#define K1_GRID 148         // one CTA per SM, single wave
#define K1_THREADS 512      // each thread owns exactly ONE float column
#define SNODES 8            // nodes per pipeline stage
#define NSTAGE 4            // ring-buffer depth (3 stages in flight)
#define STAGE_BYTES (SNODES * DDIM * 4)   // 16 KB
#define MAX_CHUNK 704       // > ceil(100000/148) = 676

#define ACC_BYTES   (ACC_ELEMS * 4)
#define OFF_STAGE   ACC_BYTES                          // 4 x 16 KB ring
#define OFF_SPK     (OFF_STAGE + NSTAGE * STAGE_BYTES) // u16 [MAX_CHUNK]
#define SMEM_BYTES  (OFF_SPK + MAX_CHUNK * 2)          // ~193.4 KB

// Scratch (allocation-free: __device__ globals)
__device__ float g_partials[K1_GRID * ACC_ELEMS];   // ~19.4 MB
__device__ float g_x[ACC_ELEMS];                    // final [64, 512]

// ---- cp.async helpers -----------------------------------------------------
__device__ __forceinline__ void cp16(uint32_t dst_smem, const void* src, int pred) {
    asm volatile(
        "{\n\t.reg .pred p;\n\t"
        "setp.ne.u32 p, %2, 0;\n\t"
        "@p cp.async.cg.shared.global [%0], [%1], 16;\n\t}"
        :: "r"(dst_smem), "l"(src), "r"(pred));
}
#define CP_COMMIT() asm volatile("cp.async.commit_group;" ::: "memory")
#define CP_WAIT(n)  asm volatile("cp.async.wait_group %0;" :: "n"(n) : "memory")

__global__ void __launch_bounds__(K1_THREADS, 1)
k1_accum(const float* __restrict__ gcn, const void* __restrict__ tp, int nnodes) {
    extern __shared__ float sacc[];                      // 128 KB accumulator
    char* sstage = (char*)sacc + OFF_STAGE;              // 64 KB stage ring
    unsigned short* spk = (unsigned short*)((char*)sacc + OFF_SPK);
    const int tid = threadIdx.x;
    const uint32_t stage_u32 =
        (uint32_t)__cvta_generic_to_shared(sstage);      // smem addr for cp.async

    // zero private accumulator
    {
        float4* z = (float4*)sacc;
#pragma unroll
        for (int i = tid; i < ACC_ELEMS / 4; i += K1_THREADS)
            z[i] = make_float4(0.f, 0.f, 0.f, 0.f);
    }

    // Runtime index-dtype detection: values are in [0, 64). If the buffer is
    // int32 but read as u64, a sample is >= 2^32 with prob 63/64 per probe.
    __shared__ int s_is64;
    if (tid == 0) {
        const unsigned long long* p = (const unsigned long long*)tp;
        int f = 1;
        for (int j = 0; j < 64; ++j)
            if (p[j] >= 64ull) { f = 0; break; }
        s_is64 = f;
    }
    __syncthreads();

    const int chunk = (nnodes + K1_GRID - 1) / K1_GRID;
    const int i0 = blockIdx.x * chunk;
    const int i1 = min(i0 + chunk, nnodes);
    const int cnt = max(i1 - i0, 0);

    // Stage this CTA's index pairs to smem, packed as u16 = b1 | (b2 << 8)
    if (s_is64) {
        const longlong2* p = (const longlong2*)tp;
        for (int j = tid; j < cnt; j += K1_THREADS) {
            longlong2 t = __ldg(p + (i0 + j));
            spk[j] = (unsigned short)(((unsigned)t.x) | (((unsigned)t.y) << 8));
        }
    } else {
        const int2* p = (const int2*)tp;
        for (int j = tid; j < cnt; j += K1_THREADS) {
            int2 t = __ldg(p + (i0 + j));
            spk[j] = (unsigned short)(((unsigned)t.x) | (((unsigned)t.y) << 8));
        }
    }
    __syncthreads();

    // ---- cp.async-pipelined hot loop --------------------------------------
    // Each stage = 8 node rows (16 KB). 3 stages continuously in flight
    // (384 x 128B lines/SM) -> DRAM latency decoupled from the RMW phase.
    const char* gbase = (const char*)(gcn) + (size_t)i0 * (DDIM * 4);
    const int T = (cnt + SNODES - 1) / SNODES;   // stages (0 if empty CTA)

    // issue stage s: 512 threads x 2 chunks of 16 B = 16 KB
#define ISSUE(s)                                                            \
    {                                                                       \
        const int _s = (s);                                                 \
        const uint32_t dbase = stage_u32 + (_s & (NSTAGE - 1)) * STAGE_BYTES;\
        _Pragma("unroll")                                                   \
        for (int q = 0; q < 2; ++q) {                                       \
            const int byte = (tid + q * K1_THREADS) * 16;                   \
            const int node = _s * SNODES + (byte >> 11);                    \
            cp16(dbase + byte,                                              \
                 gbase + ((size_t)_s * STAGE_BYTES + byte),                 \
                 node < cnt);                                               \
        }                                                                   \
    }

    // prologue: commit exactly NSTAGE-1 groups (empty commits are legal)
#pragma unroll
    for (int s = 0; s < NSTAGE - 1; ++s) {
        if (s < T) ISSUE(s);
        CP_COMMIT();
    }

    for (int s = 0; s < T; ++s) {
        CP_WAIT(NSTAGE - 2);          // group s complete (<=2 newer pending)
        __syncthreads();              // cross-thread visibility of staged data

        const float* sb = (const float*)(sstage + (s & (NSTAGE - 1)) * STAGE_BYTES);
        const int base = s * SNODES;
#pragma unroll
        for (int u = 0; u < SNODES; ++u) {
            if (base + u < cnt) {     // uniform; always true for full stages
                const float v = sb[u * DDIM + tid];
                const unsigned wrd = spk[base + u];
                const int b1 = wrd & 0xff;
                const int b2 = (wrd >> 8) & 0xff;
                sacc[b1 * DDIM + tid] += v;
                sacc[b2 * DDIM + tid] += v;
            }
        }
        __syncthreads();              // everyone done reading buf before reuse
        if (s + NSTAGE - 1 < T) ISSUE(s + NSTAGE - 1);
        CP_COMMIT();                  // keep group indexing exact at the tail
    }
#undef ISSUE

    __syncthreads();
    // flush private partial (zeros if this CTA had an empty range)
    float4* dst = (float4*)(g_partials + (size_t)blockIdx.x * ACC_ELEMS);
    const float4* src = (const float4*)sacc;
#pragma unroll
    for (int i = tid; i < ACC_ELEMS / 4; i += K1_THREADS)
        dst[i] = src[i];
}

// ---------------------------------------------------------------------------
// K2: reduce 148 partials -> g_x. Fully coalesced, deterministic order.
// ---------------------------------------------------------------------------
__global__ void __launch_bounds__(256) k2_reduce() {
    const int idx = blockIdx.x * 256 + threadIdx.x;   // 0 .. 32767
    float s = 0.f;
#pragma unroll 4
    for (int c = 0; c < K1_GRID; ++c)
        s += g_partials[(size_t)c * ACC_ELEMS + idx];
    g_x[idx] = s;
}

// ---------------------------------------------------------------------------
// K3: broadcast x[b,:] across L. Each CTA handles (b, 64 rows of L); each
// thread caches its float4 of the row in a register and streams it out with
// __stcs stores (write-once data, no L2 residency pressure).
// ---------------------------------------------------------------------------
__global__ void __launch_bounds__(256) k3_bcast(float* __restrict__ out) {
    const int b = blockIdx.y;
    const int l0 = blockIdx.x * 64;

    const int j = threadIdx.x & 127;    // float4 column 0..127
    const int r = threadIdx.x >> 7;     // row parity (0/1)
    const float4 v = __ldg((const float4*)(g_x + b * DDIM) + j);

    float4* o = (float4*)out + ((size_t)b * LSEQ + l0 + r) * (DDIM / 4) + j;
#pragma unroll
    for (int l = 0; l < 64; l += 2) {
        __stcs(o, v);
        o += 2 * (DDIM / 4);
    }
}

// ---------------------------------------------------------------------------
// Launch. Inputs (metadata order): gcn_hidden f32 [N*512], token_position
// int64/int32 [2N], batch_size, max_length, token_position2 (unused).
// ---------------------------------------------------------------------------
extern "C" void kernel_launch(void* const* d_in, const int* in_sizes, int n_in,
                              void* d_out, int out_size) {
    const float* gcn = (const float*)d_in[0];
    const void*  tp  = d_in[1];
    const int nnodes = in_sizes[0] / DDIM;   // N = 100000

    cudaFuncSetAttribute(k1_accum, cudaFuncAttributeMaxDynamicSharedMemorySize,
                         SMEM_BYTES);

    k1_accum<<<K1_GRID, K1_THREADS, SMEM_BYTES>>>(gcn, tp, nnodes);
    k2_reduce<<<ACC_ELEMS / 256, 256>>>();
    dim3 g3(LSEQ / 64, BNUM);
    k3_bcast<<<g3, 256>>>((float*)d_out);
}